// round 7
// baseline (speedup 1.0000x reference)
#include <cuda_runtime.h>
#include <cstddef>

#define BB 4
#define LL 2048
#define HH 8
#define DD 64
#define SK 40
#define NT 40
#define BHN 32
#define NSPLIT 32
#define CHUNK 64
#define KTPAD 68
#define SCALE 0.125f

// ---------------- scratch ----------------
__device__ int   g_is64;
__device__ float g_M[BHN * LL];
__device__ int   g_top[BHN * NT];
__device__ float g_pm[BHN * NSPLIT * NT];
__device__ float g_pl[BHN * NSPLIT * NT];
__device__ float g_po[BHN * NSPLIT * NT * DD];

// ---------------- detect index dtype (int64 vs int32) ----------------
__global__ void detect_idx_kernel(const long long* __restrict__ idx64) {
    int ok = 1;
    for (int i = threadIdx.x; i < 512; i += 32) {
        long long v = idx64[i];
        if (v < 0 || v >= LL) ok = 0;
    }
    unsigned m = __ballot_sync(0xffffffffu, ok);
    if (threadIdx.x == 0) g_is64 = (m == 0xffffffffu) ? 1 : 0;
}

// ---------------- sample_m (R3-proven, frozen) ----------------
__global__ void sample_m_kernel(const float* __restrict__ Q,
                                const float* __restrict__ K,
                                const void*  __restrict__ idxbuf) {
    int wid  = (blockIdx.x * blockDim.x + threadIdx.x) >> 5;
    int lane = threadIdx.x & 31;
    int l  = wid % LL;
    int bh = wid / LL;
    int b = bh >> 3, h = bh & 7;
    int g  = lane >> 3;
    int li = lane & 7;

    int ia = 0, ib = 0;
    if (g_is64) {
        const long long* p = (const long long*)idxbuf + (long long)l * SK;
        ia = (int)p[lane];
        if (lane < SK - 32) ib = (int)p[32 + lane];
    } else {
        const int* p = (const int*)idxbuf + l * SK;
        ia = p[lane];
        if (lane < SK - 32) ib = p[32 + lane];
    }

    const float* qbase = Q + (((size_t)(b * LL + l) * HH + h) << 6) + (li << 3);
    const float4 qa = ((const float4*)qbase)[0];
    const float4 qb = ((const float4*)qbase)[1];

    const size_t kstride_h = ((size_t)h << 6) + ((size_t)li << 3);
    const float* Kb = K + ((size_t)b * LL * HH << 6);

    float mx = -3e38f, sm = 0.0f;
#pragma unroll
    for (int r = 0; r < 10; r++) {
        int s = 4 * r + g;
        int j = (s < 32) ? __shfl_sync(0xffffffffu, ia, s)
                         : __shfl_sync(0xffffffffu, ib, s - 32);
        const float4* kp = (const float4*)(Kb + (((size_t)j * HH) << 6) + kstride_h);
        float4 k0 = kp[0];
        float4 k1 = kp[1];
        float p = qa.x * k0.x;
        p = fmaf(qa.y, k0.y, p);
        p = fmaf(qa.z, k0.z, p);
        p = fmaf(qa.w, k0.w, p);
        p = fmaf(qb.x, k1.x, p);
        p = fmaf(qb.y, k1.y, p);
        p = fmaf(qb.z, k1.z, p);
        p = fmaf(qb.w, k1.w, p);
        p += __shfl_xor_sync(0xffffffffu, p, 1);
        p += __shfl_xor_sync(0xffffffffu, p, 2);
        p += __shfl_xor_sync(0xffffffffu, p, 4);
        mx = fmaxf(mx, p);
        sm += p;
    }
    mx = fmaxf(mx, __shfl_xor_sync(0xffffffffu, mx, 8));
    mx = fmaxf(mx, __shfl_xor_sync(0xffffffffu, mx, 16));
    sm += __shfl_xor_sync(0xffffffffu, sm, 8);
    sm += __shfl_xor_sync(0xffffffffu, sm, 16);
    if (lane == 0) g_M[bh * LL + l] = mx - sm * (1.0f / (float)LL);
}

// ---------------- topk v3 (proven, frozen) ----------------
__global__ void topk_kernel() {
    __shared__ float sM[LL];
    int bh = blockIdx.x, lane = threadIdx.x;
    for (int i = lane; i < LL; i += 32) sM[i] = g_M[bh * LL + i];
    __syncwarp();

    int base = lane << 6;
    unsigned long long s0 = 0ull, s1 = 0ull, s2 = 0ull;
#pragma unroll 4
    for (int i = 0; i < 64; i++) {
        float x = sM[base + i];
        unsigned uv = __float_as_uint(x);
        uv ^= (uv >> 31) ? 0xffffffffu : 0x80000000u;
        unsigned long long k = ((unsigned long long)uv << 32)
                             | (unsigned)(LL - 1 - (base + i));
        if (k > s0)      { s2 = s1; s1 = s0; s0 = k; }
        else if (k > s1) { s2 = s1; s1 = k; }
        else if (k > s2) { s2 = k; }
    }

    for (int it = 0; it < NT; it++) {
        unsigned ord0 = (unsigned)(s0 >> 32);
        unsigned m1 = __reduce_max_sync(0xffffffffu, ord0);
        unsigned lowp = (ord0 == m1) ? ((unsigned)s0 + 1u) : 0u;
        unsigned m2 = __reduce_max_sync(0xffffffffu, lowp);
        int wi = LL - (int)m2;
        if (lane == 0) g_top[bh * NT + it] = wi;
        if (lane == (wi >> 6)) {
            sM[wi] = -3e38f;
            s0 = s1; s1 = s2; s2 = 0ull;
            if (s0 == 0ull) {
                for (int i = 0; i < 64; i++) {
                    float x = sM[base + i];
                    unsigned uv = __float_as_uint(x);
                    uv ^= (uv >> 31) ? 0xffffffffu : 0x80000000u;
                    unsigned long long k = ((unsigned long long)uv << 32)
                                         | (unsigned)(LL - 1 - (base + i));
                    if (k > s0)      { s2 = s1; s1 = s0; s0 = k; }
                    else if (k > s1) { s2 = s1; s1 = k; }
                    else if (k > s2) { s2 = k; }
                }
            }
        }
        __syncwarp();
    }
}

// ---------------- split-K attention v3: CHUNK=64, 54KB smem, 4 blocks/SM ----------------
__global__ void __launch_bounds__(256, 4)
attn_kernel(const float* __restrict__ Q,
            const float* __restrict__ K,
            const float* __restrict__ V) {
    extern __shared__ float smem[];
    int bh = blockIdx.x / NSPLIT, split = blockIdx.x % NSPLIT;
    int b = bh >> 3, h = bh & 7;
    int t = threadIdx.x;

    float* Qs = smem;                   // 2560
    float* Kt = Qs + NT * DD;           // 64*68 = 4352
    float* Vs = Kt + 64 * KTPAD;        // 4096
    float* Ss = Vs + CHUNK * DD;        // 2560   (total 13568 f = 54272 B)

    for (int i = t; i < NT * DD; i += 256) {
        int u = i >> 6, d = i & 63;
        int ql = g_top[bh * NT + u];
        Qs[i] = Q[(((size_t)(b * LL + ql) * HH + h) << 6) + d];
    }
    int key0 = split * CHUNK;
    for (int i = t; i < CHUNK * DD; i += 256) {
        int j = i >> 6, d = i & 63;
        size_t gbase = ((size_t)(b * LL + key0 + j) * HH + h) << 6;
        Kt[d * KTPAD + j] = K[gbase + d];
        Vs[i]             = V[gbase + d];
    }
    __syncthreads();

    // ---- phase 1: scores; 8 q-blocks x 32 float2-j-groups ----
    {
        int ublk = t >> 5;          // 0..7, 5 queries each
        int jg   = t & 31;          // float2 group over j (2 j's)
        float2 acc[5];
#pragma unroll
        for (int k = 0; k < 5; k++) acc[k] = make_float2(0.f, 0.f);
#pragma unroll 8
        for (int d = 0; d < 64; d++) {
            float2 kv = *(const float2*)(Kt + d * KTPAD + (jg << 1));
#pragma unroll
            for (int k = 0; k < 5; k++) {
                float qv = Qs[(ublk * 5 + k) * 64 + d];
                acc[k].x += qv * kv.x;
                acc[k].y += qv * kv.y;
            }
        }
#pragma unroll
        for (int k = 0; k < 5; k++) {
            int u = ublk * 5 + k;
            float2 sv = make_float2(acc[k].x * SCALE, acc[k].y * SCALE);
            *(float2*)(Ss + u * CHUNK + (jg << 1)) = sv;
        }
    }
    __syncthreads();

    // ---- phase 1.5: partial softmax (rows of 64) ----
    {
        int w = t >> 5, lane = t & 31;
        for (int r = w * 5; r < w * 5 + 5; r++) {
            float v0 = Ss[r * CHUNK + lane];
            float v1 = Ss[r * CHUNK + lane + 32];
            float m = fmaxf(v0, v1);
#pragma unroll
            for (int o = 16; o; o >>= 1) m = fmaxf(m, __shfl_xor_sync(0xffffffffu, m, o));
            float e0 = __expf(v0 - m), e1 = __expf(v1 - m);
            Ss[r * CHUNK + lane]      = e0;
            Ss[r * CHUNK + lane + 32] = e1;
            float s = e0 + e1;
#pragma unroll
            for (int o = 16; o; o >>= 1) s += __shfl_xor_sync(0xffffffffu, s, o);
            if (lane == 0) {
                g_pm[(bh * NSPLIT + split) * NT + r] = m;
                g_pl[(bh * NSPLIT + split) * NT + r] = s;
            }
        }
    }
    __syncthreads();

    // ---- phase 2: O_partial = P @ V; j halves of 32 ----
    float4 acc[5];
    int ublk = t >> 5;
    int d4   = t & 15;
    int jh   = (t >> 4) & 1;
    {
#pragma unroll
        for (int k = 0; k < 5; k++) acc[k] = make_float4(0.f, 0.f, 0.f, 0.f);
        const float4* Vs4 = (const float4*)Vs;
        int j0 = jh * 32;
#pragma unroll 4
        for (int jj = 0; jj < 32; jj++) {
            int j = j0 + jj;
            float4 vv = Vs4[j * 16 + d4];
#pragma unroll
            for (int k = 0; k < 5; k++) {
                float p = Ss[(ublk * 5 + k) * CHUNK + j];
                acc[k].x += p * vv.x;
                acc[k].y += p * vv.y;
                acc[k].z += p * vv.z;
                acc[k].w += p * vv.w;
            }
        }
    }
    __syncthreads();   // all Ss reads done before overwriting Qs/Ss with partials

    {
        float* Opart = (jh == 0) ? Qs : Ss;   // each half 2560 floats
#pragma unroll
        for (int k = 0; k < 5; k++) {
            int u = ublk * 5 + k;
            *(float4*)(Opart + u * 64 + (d4 << 2)) = acc[k];
        }
    }
    __syncthreads();

    for (int i = t; i < NT * DD; i += 256) {
        float v = Qs[i] + Ss[i];
        g_po[(size_t)(bh * NSPLIT + split) * NT * DD + i] = v;
    }
}

// ---------------- combine (proven structure; 32 splits) ----------------
__global__ void combine_kernel(float* __restrict__ out) {
    __shared__ float sw[5 * NSPLIT];
    __shared__ float sl[5];
    int bid = blockIdx.x;
    int bh = bid >> 3, uc = bid & 7;
    int b = bh >> 3, h = bh & 7;
    int t = threadIdx.x;

    if (t < 5) {
        int u = uc * 5 + t;
        float m = -3e38f;
#pragma unroll
        for (int s = 0; s < NSPLIT; s++)
            m = fmaxf(m, g_pm[(bh * NSPLIT + s) * NT + u]);
        float Ls = 0.f;
#pragma unroll
        for (int s = 0; s < NSPLIT; s++) {
            float w = __expf(g_pm[(bh * NSPLIT + s) * NT + u] - m);
            sw[t * NSPLIT + s] = w;
            Ls += g_pl[(bh * NSPLIT + s) * NT + u] * w;
        }
        sl[t] = Ls;
    }
    __syncthreads();
    for (int i = t; i < 5 * DD; i += 256) {
        int uu = i >> 6, d = i & 63;
        int u = uc * 5 + uu;
        float acc = 0.f;
#pragma unroll
        for (int s = 0; s < NSPLIT; s++)
            acc += sw[uu * NSPLIT + s] *
                   g_po[(size_t)(bh * NSPLIT + s) * NT * DD + u * DD + d];
        out[(((size_t)(b * NT + u) * HH + h) << 6) + d] = acc / sl[uu];
    }
}

// ---------------- launcher ----------------
extern "C" void kernel_launch(void* const* d_in, const int* in_sizes, int n_in,
                              void* d_out, int out_size) {
    const float* Q   = (const float*)d_in[0];
    const float* K   = (const float*)d_in[1];
    const float* V   = (const float*)d_in[2];
    const void*  idx = d_in[3];

    detect_idx_kernel<<<1, 32>>>((const long long*)idx);
    sample_m_kernel<<<(BHN * LL) / 8, 256>>>(Q, K, idx);
    topk_kernel<<<BHN, 32>>>();

    size_t smemD = (size_t)(NT * DD + 64 * KTPAD + CHUNK * DD + NT * CHUNK) * sizeof(float); // 54272
    cudaFuncSetAttribute(attn_kernel, cudaFuncAttributeMaxDynamicSharedMemorySize, (int)smemD);
    attn_kernel<<<BHN * NSPLIT, 256, smemD>>>(Q, K, V);

    combine_kernel<<<BHN * 8, 256>>>((float*)d_out);
}

// round 8
// speedup vs baseline: 1.0177x; 1.0177x over previous
#include <cuda_runtime.h>
#include <cstddef>

#define BB 4
#define LL 2048
#define HH 8
#define DD 64
#define SK 40
#define NT 40
#define BHN 32
#define NSPLIT 16
#define CHUNK 128
#define KTPAD 132
#define SCALE 0.125f

// ---------------- scratch ----------------
__device__ int   g_is64;
__device__ float g_M[BHN * LL];
__device__ int   g_top[BHN * NT];
__device__ float g_pm[BHN * NSPLIT * NT];
__device__ float g_pl[BHN * NSPLIT * NT];
__device__ float g_po[BHN * NSPLIT * NT * DD];

// ---------------- detect index dtype (int64 vs int32) ----------------
__global__ void detect_idx_kernel(const long long* __restrict__ idx64) {
    int ok = 1;
    for (int i = threadIdx.x; i < 512; i += 32) {
        long long v = idx64[i];
        if (v < 0 || v >= LL) ok = 0;
    }
    unsigned m = __ballot_sync(0xffffffffu, ok);
    if (threadIdx.x == 0) g_is64 = (m == 0xffffffffu) ? 1 : 0;
}

// ---------------- sample_m (R3-proven, frozen) ----------------
__global__ void sample_m_kernel(const float* __restrict__ Q,
                                const float* __restrict__ K,
                                const void*  __restrict__ idxbuf) {
    int wid  = (blockIdx.x * blockDim.x + threadIdx.x) >> 5;
    int lane = threadIdx.x & 31;
    int l  = wid % LL;
    int bh = wid / LL;
    int b = bh >> 3, h = bh & 7;
    int g  = lane >> 3;
    int li = lane & 7;

    int ia = 0, ib = 0;
    if (g_is64) {
        const long long* p = (const long long*)idxbuf + (long long)l * SK;
        ia = (int)p[lane];
        if (lane < SK - 32) ib = (int)p[32 + lane];
    } else {
        const int* p = (const int*)idxbuf + l * SK;
        ia = p[lane];
        if (lane < SK - 32) ib = p[32 + lane];
    }

    const float* qbase = Q + (((size_t)(b * LL + l) * HH + h) << 6) + (li << 3);
    const float4 qa = ((const float4*)qbase)[0];
    const float4 qb = ((const float4*)qbase)[1];

    const size_t kstride_h = ((size_t)h << 6) + ((size_t)li << 3);
    const float* Kb = K + ((size_t)b * LL * HH << 6);

    float mx = -3e38f, sm = 0.0f;
#pragma unroll
    for (int r = 0; r < 10; r++) {
        int s = 4 * r + g;
        int j = (s < 32) ? __shfl_sync(0xffffffffu, ia, s)
                         : __shfl_sync(0xffffffffu, ib, s - 32);
        const float4* kp = (const float4*)(Kb + (((size_t)j * HH) << 6) + kstride_h);
        float4 k0 = kp[0];
        float4 k1 = kp[1];
        float p = qa.x * k0.x;
        p = fmaf(qa.y, k0.y, p);
        p = fmaf(qa.z, k0.z, p);
        p = fmaf(qa.w, k0.w, p);
        p = fmaf(qb.x, k1.x, p);
        p = fmaf(qb.y, k1.y, p);
        p = fmaf(qb.z, k1.z, p);
        p = fmaf(qb.w, k1.w, p);
        p += __shfl_xor_sync(0xffffffffu, p, 1);
        p += __shfl_xor_sync(0xffffffffu, p, 2);
        p += __shfl_xor_sync(0xffffffffu, p, 4);
        mx = fmaxf(mx, p);
        sm += p;
    }
    mx = fmaxf(mx, __shfl_xor_sync(0xffffffffu, mx, 8));
    mx = fmaxf(mx, __shfl_xor_sync(0xffffffffu, mx, 16));
    sm += __shfl_xor_sync(0xffffffffu, sm, 8);
    sm += __shfl_xor_sync(0xffffffffu, sm, 16);
    if (lane == 0) g_M[bh * LL + l] = mx - sm * (1.0f / (float)LL);
}

// ---------------- topk v3 (proven, frozen) ----------------
__global__ void topk_kernel() {
    __shared__ float sM[LL];
    int bh = blockIdx.x, lane = threadIdx.x;
    for (int i = lane; i < LL; i += 32) sM[i] = g_M[bh * LL + i];
    __syncwarp();

    int base = lane << 6;
    unsigned long long s0 = 0ull, s1 = 0ull, s2 = 0ull;
#pragma unroll 4
    for (int i = 0; i < 64; i++) {
        float x = sM[base + i];
        unsigned uv = __float_as_uint(x);
        uv ^= (uv >> 31) ? 0xffffffffu : 0x80000000u;
        unsigned long long k = ((unsigned long long)uv << 32)
                             | (unsigned)(LL - 1 - (base + i));
        if (k > s0)      { s2 = s1; s1 = s0; s0 = k; }
        else if (k > s1) { s2 = s1; s1 = k; }
        else if (k > s2) { s2 = k; }
    }

    for (int it = 0; it < NT; it++) {
        unsigned ord0 = (unsigned)(s0 >> 32);
        unsigned m1 = __reduce_max_sync(0xffffffffu, ord0);
        unsigned lowp = (ord0 == m1) ? ((unsigned)s0 + 1u) : 0u;
        unsigned m2 = __reduce_max_sync(0xffffffffu, lowp);
        int wi = LL - (int)m2;
        if (lane == 0) g_top[bh * NT + it] = wi;
        if (lane == (wi >> 6)) {
            sM[wi] = -3e38f;
            s0 = s1; s1 = s2; s2 = 0ull;
            if (s0 == 0ull) {
                for (int i = 0; i < 64; i++) {
                    float x = sM[base + i];
                    unsigned uv = __float_as_uint(x);
                    uv ^= (uv >> 31) ? 0xffffffffu : 0x80000000u;
                    unsigned long long k = ((unsigned long long)uv << 32)
                                         | (unsigned)(LL - 1 - (base + i));
                    if (k > s0)      { s2 = s1; s1 = s0; s0 = k; }
                    else if (k > s1) { s2 = s1; s1 = k; }
                    else if (k > s2) { s2 = k; }
                }
            }
        }
        __syncwarp();
    }
}

// ---------------- split-K attention v4: R6 config + 4-wide register blocking ----------------
__global__ void attn_kernel(const float* __restrict__ Q,
                            const float* __restrict__ K,
                            const float* __restrict__ V) {
    extern __shared__ float smem[];
    int bh = blockIdx.x / NSPLIT, split = blockIdx.x % NSPLIT;
    int b = bh >> 3, h = bh & 7;
    int t = threadIdx.x;

    float* Qs = smem;                  // 2560
    float* Kt = Qs + NT * DD;          // 64*132 = 8448
    float* Vs = Kt + 64 * KTPAD;       // 8192
    float* Ss = Vs + CHUNK * DD;       // 5120   (total 24320 f = 97280 B)

    for (int i = t; i < NT * DD; i += 256) {
        int u = i >> 6, d = i & 63;
        int ql = g_top[bh * NT + u];
        Qs[i] = Q[(((size_t)(b * LL + ql) * HH + h) << 6) + d];
    }
    int key0 = split * CHUNK;
    for (int i = t; i < CHUNK * DD; i += 256) {
        int j = i >> 6, d = i & 63;
        size_t gbase = ((size_t)(b * LL + key0 + j) * HH + h) << 6;
        Kt[d * KTPAD + j] = K[gbase + d];
        Vs[i]             = V[gbase + d];
    }
    __syncthreads();

    // ---- phase 1: scores; d unrolled by 4, Q via LDS.128 broadcast ----
    {
        int ublk = t >> 5;          // 0..7, 5 queries each
        int jg   = t & 31;          // float4 group over j
        float4 acc[5];
#pragma unroll
        for (int k = 0; k < 5; k++) acc[k] = make_float4(0.f, 0.f, 0.f, 0.f);
        const float4* Kt4 = (const float4*)Kt;   // row = 33 float4
#pragma unroll 4
        for (int d = 0; d < 64; d += 4) {
            float4 kv0 = Kt4[(d + 0) * 33 + jg];
            float4 kv1 = Kt4[(d + 1) * 33 + jg];
            float4 kv2 = Kt4[(d + 2) * 33 + jg];
            float4 kv3 = Kt4[(d + 3) * 33 + jg];
#pragma unroll
            for (int k = 0; k < 5; k++) {
                float4 qv = *(const float4*)(Qs + (ublk * 5 + k) * 64 + d);
                acc[k].x += qv.x * kv0.x;
                acc[k].y += qv.x * kv0.y;
                acc[k].z += qv.x * kv0.z;
                acc[k].w += qv.x * kv0.w;
                acc[k].x += qv.y * kv1.x;
                acc[k].y += qv.y * kv1.y;
                acc[k].z += qv.y * kv1.z;
                acc[k].w += qv.y * kv1.w;
                acc[k].x += qv.z * kv2.x;
                acc[k].y += qv.z * kv2.y;
                acc[k].z += qv.z * kv2.z;
                acc[k].w += qv.z * kv2.w;
                acc[k].x += qv.w * kv3.x;
                acc[k].y += qv.w * kv3.y;
                acc[k].z += qv.w * kv3.z;
                acc[k].w += qv.w * kv3.w;
            }
        }
#pragma unroll
        for (int k = 0; k < 5; k++) {
            int u = ublk * 5 + k;
            float4 sv = make_float4(acc[k].x * SCALE, acc[k].y * SCALE,
                                    acc[k].z * SCALE, acc[k].w * SCALE);
            *(float4*)(Ss + u * CHUNK + (jg << 2)) = sv;
        }
    }
    __syncthreads();

    // ---- phase 1.5: partial softmax ----
    {
        int w = t >> 5, lane = t & 31;
        for (int r = w * 5; r < w * 5 + 5; r++) {
            float v0 = Ss[r * CHUNK + lane];
            float v1 = Ss[r * CHUNK + lane + 32];
            float v2 = Ss[r * CHUNK + lane + 64];
            float v3 = Ss[r * CHUNK + lane + 96];
            float m = fmaxf(fmaxf(v0, v1), fmaxf(v2, v3));
#pragma unroll
            for (int o = 16; o; o >>= 1) m = fmaxf(m, __shfl_xor_sync(0xffffffffu, m, o));
            float e0 = __expf(v0 - m), e1 = __expf(v1 - m);
            float e2 = __expf(v2 - m), e3 = __expf(v3 - m);
            Ss[r * CHUNK + lane]      = e0;
            Ss[r * CHUNK + lane + 32] = e1;
            Ss[r * CHUNK + lane + 64] = e2;
            Ss[r * CHUNK + lane + 96] = e3;
            float s = e0 + e1 + e2 + e3;
#pragma unroll
            for (int o = 16; o; o >>= 1) s += __shfl_xor_sync(0xffffffffu, s, o);
            if (lane == 0) {
                g_pm[(bh * NSPLIT + split) * NT + r] = m;
                g_pl[(bh * NSPLIT + split) * NT + r] = s;
            }
        }
    }
    __syncthreads();

    // ---- phase 2: O_partial = P @ V; j unrolled by 4, P via LDS.128 ----
    {
        int ublk = t >> 5;
        int d4   = t & 15;
        int jh   = (t >> 4) & 1;
        float4 acc[5];
#pragma unroll
        for (int k = 0; k < 5; k++) acc[k] = make_float4(0.f, 0.f, 0.f, 0.f);
        const float4* Vs4 = (const float4*)Vs;
        int j0 = jh * 64;
#pragma unroll 4
        for (int jj = 0; jj < 64; jj += 4) {
            int j = j0 + jj;
            float4 vv0 = Vs4[(j + 0) * 16 + d4];
            float4 vv1 = Vs4[(j + 1) * 16 + d4];
            float4 vv2 = Vs4[(j + 2) * 16 + d4];
            float4 vv3 = Vs4[(j + 3) * 16 + d4];
#pragma unroll
            for (int k = 0; k < 5; k++) {
                float4 p = *(const float4*)(Ss + (ublk * 5 + k) * CHUNK + j);
                acc[k].x += p.x * vv0.x;
                acc[k].y += p.x * vv0.y;
                acc[k].z += p.x * vv0.z;
                acc[k].w += p.x * vv0.w;
                acc[k].x += p.y * vv1.x;
                acc[k].y += p.y * vv1.y;
                acc[k].z += p.y * vv1.z;
                acc[k].w += p.y * vv1.w;
                acc[k].x += p.z * vv2.x;
                acc[k].y += p.z * vv2.y;
                acc[k].z += p.z * vv2.z;
                acc[k].w += p.z * vv2.w;
                acc[k].x += p.w * vv3.x;
                acc[k].y += p.w * vv3.y;
                acc[k].z += p.w * vv3.z;
                acc[k].w += p.w * vv3.w;
            }
        }
        __syncthreads();   // all Ss/Kt readers done before overwrite
        float* Opart = Kt;
#pragma unroll
        for (int k = 0; k < 5; k++) {
            int u = ublk * 5 + k;
            *(float4*)(Opart + (jh * NT + u) * 64 + (d4 << 2)) = acc[k];
        }
    }
    __syncthreads();

    for (int i = t; i < NT * DD; i += 256) {
        float v = Kt[i] + Kt[NT * DD + i];
        g_po[(size_t)(bh * NSPLIT + split) * NT * DD + i] = v;
    }
}

// ---------------- combine v2 (proven, frozen) ----------------
__global__ void combine_kernel(float* __restrict__ out) {
    __shared__ float sw[5 * NSPLIT];
    __shared__ float sl[5];
    int bid = blockIdx.x;
    int bh = bid >> 3, uc = bid & 7;
    int b = bh >> 3, h = bh & 7;
    int t = threadIdx.x;

    if (t < 5) {
        int u = uc * 5 + t;
        float m = -3e38f;
#pragma unroll
        for (int s = 0; s < NSPLIT; s++)
            m = fmaxf(m, g_pm[(bh * NSPLIT + s) * NT + u]);
        float Ls = 0.f;
#pragma unroll
        for (int s = 0; s < NSPLIT; s++) {
            float w = __expf(g_pm[(bh * NSPLIT + s) * NT + u] - m);
            sw[t * NSPLIT + s] = w;
            Ls += g_pl[(bh * NSPLIT + s) * NT + u] * w;
        }
        sl[t] = Ls;
    }
    __syncthreads();
    for (int i = t; i < 5 * DD; i += 256) {
        int uu = i >> 6, d = i & 63;
        int u = uc * 5 + uu;
        float acc = 0.f;
#pragma unroll
        for (int s = 0; s < NSPLIT; s++)
            acc += sw[uu * NSPLIT + s] *
                   g_po[(size_t)(bh * NSPLIT + s) * NT * DD + u * DD + d];
        out[(((size_t)(b * NT + u) * HH + h) << 6) + d] = acc / sl[uu];
    }
}

// ---------------- launcher ----------------
extern "C" void kernel_launch(void* const* d_in, const int* in_sizes, int n_in,
                              void* d_out, int out_size) {
    const float* Q   = (const float*)d_in[0];
    const float* K   = (const float*)d_in[1];
    const float* V   = (const float*)d_in[2];
    const void*  idx = d_in[3];

    detect_idx_kernel<<<1, 32>>>((const long long*)idx);
    sample_m_kernel<<<(BHN * LL) / 8, 256>>>(Q, K, idx);
    topk_kernel<<<BHN, 32>>>();

    size_t smemD = (size_t)(NT * DD + 64 * KTPAD + CHUNK * DD + NT * CHUNK) * sizeof(float); // 97280
    cudaFuncSetAttribute(attn_kernel, cudaFuncAttributeMaxDynamicSharedMemorySize, (int)smemD);
    attn_kernel<<<BHN * NSPLIT, 256, smemD>>>(Q, K, V);

    combine_kernel<<<BHN * 8, 256>>>((float*)d_out);
}

// round 9
// speedup vs baseline: 1.0324x; 1.0144x over previous
#include <cuda_runtime.h>
#include <cstddef>

#define BB 4
#define LL 2048
#define HH 8
#define DD 64
#define SK 40
#define NT 40
#define BHN 32
#define NSPLIT 16
#define CHUNK 128
#define KTPAD 132
#define SCALE 0.125f

// ---------------- scratch ----------------
__device__ int   g_is64;
__device__ float g_M[BHN * LL];
__device__ int   g_top[BHN * NT];
__device__ float g_pm[BHN * NSPLIT * NT];
__device__ float g_pl[BHN * NSPLIT * NT];
__device__ float g_po[BHN * NSPLIT * NT * DD];

// ---------------- detect index dtype (int64 vs int32) ----------------
__global__ void detect_idx_kernel(const long long* __restrict__ idx64) {
    int ok = 1;
    for (int i = threadIdx.x; i < 512; i += 32) {
        long long v = idx64[i];
        if (v < 0 || v >= LL) ok = 0;
    }
    unsigned m = __ballot_sync(0xffffffffu, ok);
    if (threadIdx.x == 0) g_is64 = (m == 0xffffffffu) ? 1 : 0;
}

// ---------------- sample_m (R3-proven, frozen) ----------------
__global__ void sample_m_kernel(const float* __restrict__ Q,
                                const float* __restrict__ K,
                                const void*  __restrict__ idxbuf) {
    int wid  = (blockIdx.x * blockDim.x + threadIdx.x) >> 5;
    int lane = threadIdx.x & 31;
    int l  = wid % LL;
    int bh = wid / LL;
    int b = bh >> 3, h = bh & 7;
    int g  = lane >> 3;
    int li = lane & 7;

    int ia = 0, ib = 0;
    if (g_is64) {
        const long long* p = (const long long*)idxbuf + (long long)l * SK;
        ia = (int)p[lane];
        if (lane < SK - 32) ib = (int)p[32 + lane];
    } else {
        const int* p = (const int*)idxbuf + l * SK;
        ia = p[lane];
        if (lane < SK - 32) ib = p[32 + lane];
    }

    const float* qbase = Q + (((size_t)(b * LL + l) * HH + h) << 6) + (li << 3);
    const float4 qa = ((const float4*)qbase)[0];
    const float4 qb = ((const float4*)qbase)[1];

    const size_t kstride_h = ((size_t)h << 6) + ((size_t)li << 3);
    const float* Kb = K + ((size_t)b * LL * HH << 6);

    float mx = -3e38f, sm = 0.0f;
#pragma unroll
    for (int r = 0; r < 10; r++) {
        int s = 4 * r + g;
        int j = (s < 32) ? __shfl_sync(0xffffffffu, ia, s)
                         : __shfl_sync(0xffffffffu, ib, s - 32);
        const float4* kp = (const float4*)(Kb + (((size_t)j * HH) << 6) + kstride_h);
        float4 k0 = kp[0];
        float4 k1 = kp[1];
        float p = qa.x * k0.x;
        p = fmaf(qa.y, k0.y, p);
        p = fmaf(qa.z, k0.z, p);
        p = fmaf(qa.w, k0.w, p);
        p = fmaf(qb.x, k1.x, p);
        p = fmaf(qb.y, k1.y, p);
        p = fmaf(qb.z, k1.z, p);
        p = fmaf(qb.w, k1.w, p);
        p += __shfl_xor_sync(0xffffffffu, p, 1);
        p += __shfl_xor_sync(0xffffffffu, p, 2);
        p += __shfl_xor_sync(0xffffffffu, p, 4);
        mx = fmaxf(mx, p);
        sm += p;
    }
    mx = fmaxf(mx, __shfl_xor_sync(0xffffffffu, mx, 8));
    mx = fmaxf(mx, __shfl_xor_sync(0xffffffffu, mx, 16));
    sm += __shfl_xor_sync(0xffffffffu, sm, 8);
    sm += __shfl_xor_sync(0xffffffffu, sm, 16);
    if (lane == 0) g_M[bh * LL + l] = mx - sm * (1.0f / (float)LL);
}

// ---------------- topk v3 (proven, frozen) ----------------
__global__ void topk_kernel() {
    __shared__ float sM[LL];
    int bh = blockIdx.x, lane = threadIdx.x;
    for (int i = lane; i < LL; i += 32) sM[i] = g_M[bh * LL + i];
    __syncwarp();

    int base = lane << 6;
    unsigned long long s0 = 0ull, s1 = 0ull, s2 = 0ull;
#pragma unroll 4
    for (int i = 0; i < 64; i++) {
        float x = sM[base + i];
        unsigned uv = __float_as_uint(x);
        uv ^= (uv >> 31) ? 0xffffffffu : 0x80000000u;
        unsigned long long k = ((unsigned long long)uv << 32)
                             | (unsigned)(LL - 1 - (base + i));
        if (k > s0)      { s2 = s1; s1 = s0; s0 = k; }
        else if (k > s1) { s2 = s1; s1 = k; }
        else if (k > s2) { s2 = k; }
    }

    for (int it = 0; it < NT; it++) {
        unsigned ord0 = (unsigned)(s0 >> 32);
        unsigned m1 = __reduce_max_sync(0xffffffffu, ord0);
        unsigned lowp = (ord0 == m1) ? ((unsigned)s0 + 1u) : 0u;
        unsigned m2 = __reduce_max_sync(0xffffffffu, lowp);
        int wi = LL - (int)m2;
        if (lane == 0) g_top[bh * NT + it] = wi;
        if (lane == (wi >> 6)) {
            sM[wi] = -3e38f;
            s0 = s1; s1 = s2; s2 = 0ull;
            if (s0 == 0ull) {
                for (int i = 0; i < 64; i++) {
                    float x = sM[base + i];
                    unsigned uv = __float_as_uint(x);
                    uv ^= (uv >> 31) ? 0xffffffffu : 0x80000000u;
                    unsigned long long k = ((unsigned long long)uv << 32)
                                         | (unsigned)(LL - 1 - (base + i));
                    if (k > s0)      { s2 = s1; s1 = s0; s0 = k; }
                    else if (k > s1) { s2 = s1; s1 = k; }
                    else if (k > s2) { s2 = k; }
                }
            }
        }
        __syncwarp();
    }
}

// ---------------- split-K attention v5: software-pipelined, 2 blocks/SM ----------------
__global__ void __launch_bounds__(256, 2)
attn_kernel(const float* __restrict__ Q,
            const float* __restrict__ K,
            const float* __restrict__ V) {
    extern __shared__ float smem[];
    int bh = blockIdx.x / NSPLIT, split = blockIdx.x % NSPLIT;
    int b = bh >> 3, h = bh & 7;
    int t = threadIdx.x;

    float* Qs = smem;                  // 2560
    float* Kt = Qs + NT * DD;          // 64*132 = 8448
    float* Vs = Kt + 64 * KTPAD;       // 8192
    float* Ss = Vs + CHUNK * DD;       // 5120   (97280 B)

    // Q staging (float4)
    for (int i = t; i < NT * 16; i += 256) {
        int u = i >> 4, c = i & 15;
        int ql = g_top[bh * NT + u];
        ((float4*)Qs)[i] =
            ((const float4*)Q)[(((size_t)(b * LL + ql) * HH + h) << 4) + c];
    }
    int key0 = split * CHUNK;
    // V staging (float4)
    for (int i = t; i < CHUNK * 16; i += 256) {
        int j = i >> 4, c = i & 15;
        ((float4*)Vs)[i] =
            ((const float4*)V)[(((size_t)(b * LL + key0 + j) * HH + h) << 4) + c];
    }
    // K staging transposed (scalar, proven)
    for (int i = t; i < CHUNK * DD; i += 256) {
        int j = i >> 6, d = i & 63;
        Kt[d * KTPAD + j] = K[(((size_t)(b * LL + key0 + j) * HH + h) << 6) + d];
    }
    __syncthreads();

    // ---- phase 1: scores; d by 4, K loads double-buffered ----
    {
        int ublk = t >> 5;          // 0..7, 5 queries each
        int jg   = t & 31;          // float4 group over j
        float4 acc[5];
#pragma unroll
        for (int k = 0; k < 5; k++) acc[k] = make_float4(0.f, 0.f, 0.f, 0.f);
        const float4* Kt4 = (const float4*)Kt;   // row = 33 float4
        float4 kv[4], kvn[4];
#pragma unroll
        for (int c = 0; c < 4; c++) kv[c] = Kt4[c * 33 + jg];
#pragma unroll
        for (int d = 0; d < 64; d += 4) {
            int dn = (d + 4) & 63;   // wrap: last prefetch unused
#pragma unroll
            for (int c = 0; c < 4; c++) kvn[c] = Kt4[(dn + c) * 33 + jg];
#pragma unroll
            for (int k = 0; k < 5; k++) {
                float4 qv = *(const float4*)(Qs + (ublk * 5 + k) * 64 + d);
                acc[k].x += qv.x * kv[0].x;
                acc[k].y += qv.x * kv[0].y;
                acc[k].z += qv.x * kv[0].z;
                acc[k].w += qv.x * kv[0].w;
                acc[k].x += qv.y * kv[1].x;
                acc[k].y += qv.y * kv[1].y;
                acc[k].z += qv.y * kv[1].z;
                acc[k].w += qv.y * kv[1].w;
                acc[k].x += qv.z * kv[2].x;
                acc[k].y += qv.z * kv[2].y;
                acc[k].z += qv.z * kv[2].z;
                acc[k].w += qv.z * kv[2].w;
                acc[k].x += qv.w * kv[3].x;
                acc[k].y += qv.w * kv[3].y;
                acc[k].z += qv.w * kv[3].z;
                acc[k].w += qv.w * kv[3].w;
            }
#pragma unroll
            for (int c = 0; c < 4; c++) kv[c] = kvn[c];
        }
#pragma unroll
        for (int k = 0; k < 5; k++) {
            int u = ublk * 5 + k;
            float4 sv = make_float4(acc[k].x * SCALE, acc[k].y * SCALE,
                                    acc[k].z * SCALE, acc[k].w * SCALE);
            *(float4*)(Ss + u * CHUNK + (jg << 2)) = sv;
        }
    }
    __syncthreads();

    // ---- phase 1.5: partial softmax ----
    {
        int w = t >> 5, lane = t & 31;
        for (int r = w * 5; r < w * 5 + 5; r++) {
            float v0 = Ss[r * CHUNK + lane];
            float v1 = Ss[r * CHUNK + lane + 32];
            float v2 = Ss[r * CHUNK + lane + 64];
            float v3 = Ss[r * CHUNK + lane + 96];
            float m = fmaxf(fmaxf(v0, v1), fmaxf(v2, v3));
#pragma unroll
            for (int o = 16; o; o >>= 1) m = fmaxf(m, __shfl_xor_sync(0xffffffffu, m, o));
            float e0 = __expf(v0 - m), e1 = __expf(v1 - m);
            float e2 = __expf(v2 - m), e3 = __expf(v3 - m);
            Ss[r * CHUNK + lane]      = e0;
            Ss[r * CHUNK + lane + 32] = e1;
            Ss[r * CHUNK + lane + 64] = e2;
            Ss[r * CHUNK + lane + 96] = e3;
            float s = e0 + e1 + e2 + e3;
#pragma unroll
            for (int o = 16; o; o >>= 1) s += __shfl_xor_sync(0xffffffffu, s, o);
            if (lane == 0) {
                g_pm[(bh * NSPLIT + split) * NT + r] = m;
                g_pl[(bh * NSPLIT + split) * NT + r] = s;
            }
        }
    }
    __syncthreads();

    // ---- phase 2: O_partial = P @ V; j by 4, V loads double-buffered ----
    {
        int ublk = t >> 5;
        int d4   = t & 15;
        int jh   = (t >> 4) & 1;
        float4 acc[5];
#pragma unroll
        for (int k = 0; k < 5; k++) acc[k] = make_float4(0.f, 0.f, 0.f, 0.f);
        const float4* Vs4 = (const float4*)Vs;
        int j0 = jh * 64;
        float4 vv[4], vvn[4];
#pragma unroll
        for (int c = 0; c < 4; c++) vv[c] = Vs4[(j0 + c) * 16 + d4];
#pragma unroll
        for (int jj = 0; jj < 64; jj += 4) {
            int j = j0 + jj;
            int jn = j0 + ((jj + 4) & 63);
#pragma unroll
            for (int c = 0; c < 4; c++) vvn[c] = Vs4[(jn + c) * 16 + d4];
#pragma unroll
            for (int k = 0; k < 5; k++) {
                float4 p = *(const float4*)(Ss + (ublk * 5 + k) * CHUNK + j);
                acc[k].x += p.x * vv[0].x;
                acc[k].y += p.x * vv[0].y;
                acc[k].z += p.x * vv[0].z;
                acc[k].w += p.x * vv[0].w;
                acc[k].x += p.y * vv[1].x;
                acc[k].y += p.y * vv[1].y;
                acc[k].z += p.y * vv[1].z;
                acc[k].w += p.y * vv[1].w;
                acc[k].x += p.z * vv[2].x;
                acc[k].y += p.z * vv[2].y;
                acc[k].z += p.z * vv[2].z;
                acc[k].w += p.z * vv[2].w;
                acc[k].x += p.w * vv[3].x;
                acc[k].y += p.w * vv[3].y;
                acc[k].z += p.w * vv[3].z;
                acc[k].w += p.w * vv[3].w;
            }
#pragma unroll
            for (int c = 0; c < 4; c++) vv[c] = vvn[c];
        }
        __syncthreads();   // all Ss/Kt readers done before overwrite
        float* Opart = Kt;
#pragma unroll
        for (int k = 0; k < 5; k++) {
            int u = ublk * 5 + k;
            *(float4*)(Opart + (jh * NT + u) * 64 + (d4 << 2)) = acc[k];
        }
    }
    __syncthreads();

    // partial add + write (float4)
    {
        const float4* Kt4f = (const float4*)Kt;
        float4* po4 = (float4*)(g_po + (size_t)(bh * NSPLIT + split) * NT * DD);
        for (int i = t; i < NT * 16; i += 256) {
            float4 a = Kt4f[i];
            float4 c = Kt4f[NT * 16 + i];
            a.x += c.x; a.y += c.y; a.z += c.z; a.w += c.w;
            po4[i] = a;
        }
    }
}

// ---------------- combine v2 (proven, frozen) ----------------
__global__ void combine_kernel(float* __restrict__ out) {
    __shared__ float sw[5 * NSPLIT];
    __shared__ float sl[5];
    int bid = blockIdx.x;
    int bh = bid >> 3, uc = bid & 7;
    int b = bh >> 3, h = bh & 7;
    int t = threadIdx.x;

    if (t < 5) {
        int u = uc * 5 + t;
        float m = -3e38f;
#pragma unroll
        for (int s = 0; s < NSPLIT; s++)
            m = fmaxf(m, g_pm[(bh * NSPLIT + s) * NT + u]);
        float Ls = 0.f;
#pragma unroll
        for (int s = 0; s < NSPLIT; s++) {
            float w = __expf(g_pm[(bh * NSPLIT + s) * NT + u] - m);
            sw[t * NSPLIT + s] = w;
            Ls += g_pl[(bh * NSPLIT + s) * NT + u] * w;
        }
        sl[t] = Ls;
    }
    __syncthreads();
    for (int i = t; i < 5 * DD; i += 256) {
        int uu = i >> 6, d = i & 63;
        int u = uc * 5 + uu;
        float acc = 0.f;
#pragma unroll
        for (int s = 0; s < NSPLIT; s++)
            acc += sw[uu * NSPLIT + s] *
                   g_po[(size_t)(bh * NSPLIT + s) * NT * DD + u * DD + d];
        out[(((size_t)(b * NT + u) * HH + h) << 6) + d] = acc / sl[uu];
    }
}

// ---------------- launcher ----------------
extern "C" void kernel_launch(void* const* d_in, const int* in_sizes, int n_in,
                              void* d_out, int out_size) {
    const float* Q   = (const float*)d_in[0];
    const float* K   = (const float*)d_in[1];
    const float* V   = (const float*)d_in[2];
    const void*  idx = d_in[3];

    detect_idx_kernel<<<1, 32>>>((const long long*)idx);
    sample_m_kernel<<<(BHN * LL) / 8, 256>>>(Q, K, idx);
    topk_kernel<<<BHN, 32>>>();

    size_t smemD = (size_t)(NT * DD + 64 * KTPAD + CHUNK * DD + NT * CHUNK) * sizeof(float); // 97280
    cudaFuncSetAttribute(attn_kernel, cudaFuncAttributeMaxDynamicSharedMemorySize, (int)smemD);
    attn_kernel<<<BHN * NSPLIT, 256, smemD>>>(Q, K, V);

    combine_kernel<<<BHN * 8, 256>>>((float*)d_out);
}

// round 10
// speedup vs baseline: 1.0369x; 1.0044x over previous
#include <cuda_runtime.h>
#include <cstddef>

#define BB 4
#define LL 2048
#define HH 8
#define DD 64
#define SK 40
#define NT 40
#define BHN 32
#define NSPLIT 16
#define CHUNK 128
#define KTPAD 132
#define SCALE 0.125f

// ---------------- scratch ----------------
__device__ int   g_is64;
__device__ float g_M[BHN * LL];
__device__ int   g_top[BHN * NT];
__device__ float g_pm[BHN * NSPLIT * NT];
__device__ float g_pl[BHN * NSPLIT * NT];
__device__ float g_po[BHN * NSPLIT * NT * DD];

// ---------------- detect index dtype (int64 vs int32) ----------------
__global__ void detect_idx_kernel(const long long* __restrict__ idx64) {
    int ok = 1;
    for (int i = threadIdx.x; i < 512; i += 32) {
        long long v = idx64[i];
        if (v < 0 || v >= LL) ok = 0;
    }
    unsigned m = __ballot_sync(0xffffffffu, ok);
    if (threadIdx.x == 0) g_is64 = (m == 0xffffffffu) ? 1 : 0;
}

// ---------------- sample_m (R3-proven, frozen) ----------------
__global__ void sample_m_kernel(const float* __restrict__ Q,
                                const float* __restrict__ K,
                                const void*  __restrict__ idxbuf) {
    int wid  = (blockIdx.x * blockDim.x + threadIdx.x) >> 5;
    int lane = threadIdx.x & 31;
    int l  = wid % LL;
    int bh = wid / LL;
    int b = bh >> 3, h = bh & 7;
    int g  = lane >> 3;
    int li = lane & 7;

    int ia = 0, ib = 0;
    if (g_is64) {
        const long long* p = (const long long*)idxbuf + (long long)l * SK;
        ia = (int)p[lane];
        if (lane < SK - 32) ib = (int)p[32 + lane];
    } else {
        const int* p = (const int*)idxbuf + l * SK;
        ia = p[lane];
        if (lane < SK - 32) ib = p[32 + lane];
    }

    const float* qbase = Q + (((size_t)(b * LL + l) * HH + h) << 6) + (li << 3);
    const float4 qa = ((const float4*)qbase)[0];
    const float4 qb = ((const float4*)qbase)[1];

    const size_t kstride_h = ((size_t)h << 6) + ((size_t)li << 3);
    const float* Kb = K + ((size_t)b * LL * HH << 6);

    float mx = -3e38f, sm = 0.0f;
#pragma unroll
    for (int r = 0; r < 10; r++) {
        int s = 4 * r + g;
        int j = (s < 32) ? __shfl_sync(0xffffffffu, ia, s)
                         : __shfl_sync(0xffffffffu, ib, s - 32);
        const float4* kp = (const float4*)(Kb + (((size_t)j * HH) << 6) + kstride_h);
        float4 k0 = kp[0];
        float4 k1 = kp[1];
        float p = qa.x * k0.x;
        p = fmaf(qa.y, k0.y, p);
        p = fmaf(qa.z, k0.z, p);
        p = fmaf(qa.w, k0.w, p);
        p = fmaf(qb.x, k1.x, p);
        p = fmaf(qb.y, k1.y, p);
        p = fmaf(qb.z, k1.z, p);
        p = fmaf(qb.w, k1.w, p);
        p += __shfl_xor_sync(0xffffffffu, p, 1);
        p += __shfl_xor_sync(0xffffffffu, p, 2);
        p += __shfl_xor_sync(0xffffffffu, p, 4);
        mx = fmaxf(mx, p);
        sm += p;
    }
    mx = fmaxf(mx, __shfl_xor_sync(0xffffffffu, mx, 8));
    mx = fmaxf(mx, __shfl_xor_sync(0xffffffffu, mx, 16));
    sm += __shfl_xor_sync(0xffffffffu, sm, 8);
    sm += __shfl_xor_sync(0xffffffffu, sm, 16);
    if (lane == 0) g_M[bh * LL + l] = mx - sm * (1.0f / (float)LL);
}

// ---------------- topk v3 (proven, frozen) ----------------
__global__ void topk_kernel() {
    __shared__ float sM[LL];
    int bh = blockIdx.x, lane = threadIdx.x;
    for (int i = lane; i < LL; i += 32) sM[i] = g_M[bh * LL + i];
    __syncwarp();

    int base = lane << 6;
    unsigned long long s0 = 0ull, s1 = 0ull, s2 = 0ull;
#pragma unroll 4
    for (int i = 0; i < 64; i++) {
        float x = sM[base + i];
        unsigned uv = __float_as_uint(x);
        uv ^= (uv >> 31) ? 0xffffffffu : 0x80000000u;
        unsigned long long k = ((unsigned long long)uv << 32)
                             | (unsigned)(LL - 1 - (base + i));
        if (k > s0)      { s2 = s1; s1 = s0; s0 = k; }
        else if (k > s1) { s2 = s1; s1 = k; }
        else if (k > s2) { s2 = k; }
    }

    for (int it = 0; it < NT; it++) {
        unsigned ord0 = (unsigned)(s0 >> 32);
        unsigned m1 = __reduce_max_sync(0xffffffffu, ord0);
        unsigned lowp = (ord0 == m1) ? ((unsigned)s0 + 1u) : 0u;
        unsigned m2 = __reduce_max_sync(0xffffffffu, lowp);
        int wi = LL - (int)m2;
        if (lane == 0) g_top[bh * NT + it] = wi;
        if (lane == (wi >> 6)) {
            sM[wi] = -3e38f;
            s0 = s1; s1 = s2; s2 = 0ull;
            if (s0 == 0ull) {
                for (int i = 0; i < 64; i++) {
                    float x = sM[base + i];
                    unsigned uv = __float_as_uint(x);
                    uv ^= (uv >> 31) ? 0xffffffffu : 0x80000000u;
                    unsigned long long k = ((unsigned long long)uv << 32)
                                         | (unsigned)(LL - 1 - (base + i));
                    if (k > s0)      { s2 = s1; s1 = s0; s0 = k; }
                    else if (k > s1) { s2 = s1; s1 = k; }
                    else if (k > s2) { s2 = k; }
                }
            }
        }
        __syncwarp();
    }
}

// ---------------- split-K attention v6: deferred V staging, 63KB smem, 3 blocks/SM ----------------
__global__ void __launch_bounds__(256, 3)
attn_kernel(const float* __restrict__ Q,
            const float* __restrict__ K,
            const float* __restrict__ V) {
    extern __shared__ float smem[];
    int bh = blockIdx.x / NSPLIT, split = blockIdx.x % NSPLIT;
    int b = bh >> 3, h = bh & 7;
    int t = threadIdx.x;

    float* Qs = smem;                  // 2560
    float* KV = Qs + NT * DD;          // 8448: Kt (64x132) in ph1, then V (128x64) in ph2
    float* Ss = KV + 64 * KTPAD;       // 5120   (total 16128 f = 64512 B)

    // Q staging (float4)
    for (int i = t; i < NT * 16; i += 256) {
        int u = i >> 4, c = i & 15;
        int ql = g_top[bh * NT + u];
        ((float4*)Qs)[i] =
            ((const float4*)Q)[(((size_t)(b * LL + ql) * HH + h) << 4) + c];
    }
    int key0 = split * CHUNK;
    // K staging transposed (scalar, proven)
    for (int i = t; i < CHUNK * DD; i += 256) {
        int j = i >> 6, d = i & 63;
        KV[d * KTPAD + j] = K[(((size_t)(b * LL + key0 + j) * HH + h) << 6) + d];
    }
    __syncthreads();

    // ---- phase 1: scores; d unrolled by 4 (R8-proven math order) ----
    {
        int ublk = t >> 5;          // 0..7, 5 queries each
        int jg   = t & 31;          // float4 group over j
        float4 acc[5];
#pragma unroll
        for (int k = 0; k < 5; k++) acc[k] = make_float4(0.f, 0.f, 0.f, 0.f);
        const float4* Kt4 = (const float4*)KV;   // row = 33 float4
#pragma unroll 4
        for (int d = 0; d < 64; d += 4) {
            float4 kv0 = Kt4[(d + 0) * 33 + jg];
            float4 kv1 = Kt4[(d + 1) * 33 + jg];
            float4 kv2 = Kt4[(d + 2) * 33 + jg];
            float4 kv3 = Kt4[(d + 3) * 33 + jg];
#pragma unroll
            for (int k = 0; k < 5; k++) {
                float4 qv = *(const float4*)(Qs + (ublk * 5 + k) * 64 + d);
                acc[k].x += qv.x * kv0.x;
                acc[k].y += qv.x * kv0.y;
                acc[k].z += qv.x * kv0.z;
                acc[k].w += qv.x * kv0.w;
                acc[k].x += qv.y * kv1.x;
                acc[k].y += qv.y * kv1.y;
                acc[k].z += qv.y * kv1.z;
                acc[k].w += qv.y * kv1.w;
                acc[k].x += qv.z * kv2.x;
                acc[k].y += qv.z * kv2.y;
                acc[k].z += qv.z * kv2.z;
                acc[k].w += qv.z * kv2.w;
                acc[k].x += qv.w * kv3.x;
                acc[k].y += qv.w * kv3.y;
                acc[k].z += qv.w * kv3.z;
                acc[k].w += qv.w * kv3.w;
            }
        }
#pragma unroll
        for (int k = 0; k < 5; k++) {
            int u = ublk * 5 + k;
            float4 sv = make_float4(acc[k].x * SCALE, acc[k].y * SCALE,
                                    acc[k].z * SCALE, acc[k].w * SCALE);
            *(float4*)(Ss + u * CHUNK + (jg << 2)) = sv;
        }
    }
    __syncwarp();   // softmax rows below are this warp's own ph1 rows

    // ---- phase 1.5: partial softmax (warp-local rows) ----
    {
        int w = t >> 5, lane = t & 31;
        for (int r = w * 5; r < w * 5 + 5; r++) {
            float v0 = Ss[r * CHUNK + lane];
            float v1 = Ss[r * CHUNK + lane + 32];
            float v2 = Ss[r * CHUNK + lane + 64];
            float v3 = Ss[r * CHUNK + lane + 96];
            float m = fmaxf(fmaxf(v0, v1), fmaxf(v2, v3));
#pragma unroll
            for (int o = 16; o; o >>= 1) m = fmaxf(m, __shfl_xor_sync(0xffffffffu, m, o));
            float e0 = __expf(v0 - m), e1 = __expf(v1 - m);
            float e2 = __expf(v2 - m), e3 = __expf(v3 - m);
            Ss[r * CHUNK + lane]      = e0;
            Ss[r * CHUNK + lane + 32] = e1;
            Ss[r * CHUNK + lane + 64] = e2;
            Ss[r * CHUNK + lane + 96] = e3;
            float s = e0 + e1 + e2 + e3;
#pragma unroll
            for (int o = 16; o; o >>= 1) s += __shfl_xor_sync(0xffffffffu, s, o);
            if (lane == 0) {
                g_pm[(bh * NSPLIT + split) * NT + r] = m;
                g_pl[(bh * NSPLIT + split) * NT + r] = s;
            }
        }
    }
    __syncthreads();   // all ph1 Kt reads complete before V overwrites KV

    // ---- deferred V staging into KV (float4, linear [j][d]) ----
    for (int i = t; i < CHUNK * 16; i += 256) {
        int j = i >> 4, c = i & 15;
        ((float4*)KV)[i] =
            ((const float4*)V)[(((size_t)(b * LL + key0 + j) * HH + h) << 4) + c];
    }
    __syncthreads();

    // ---- phase 2: O_partial = P @ V; j unrolled by 4 (R8-proven math order) ----
    {
        int ublk = t >> 5;
        int d4   = t & 15;
        int jh   = (t >> 4) & 1;
        float4 acc[5];
#pragma unroll
        for (int k = 0; k < 5; k++) acc[k] = make_float4(0.f, 0.f, 0.f, 0.f);
        const float4* Vs4 = (const float4*)KV;   // row = 16 float4
        int j0 = jh * 64;
#pragma unroll 4
        for (int jj = 0; jj < 64; jj += 4) {
            int j = j0 + jj;
            float4 vv0 = Vs4[(j + 0) * 16 + d4];
            float4 vv1 = Vs4[(j + 1) * 16 + d4];
            float4 vv2 = Vs4[(j + 2) * 16 + d4];
            float4 vv3 = Vs4[(j + 3) * 16 + d4];
#pragma unroll
            for (int k = 0; k < 5; k++) {
                float4 p = *(const float4*)(Ss + (ublk * 5 + k) * CHUNK + j);
                acc[k].x += p.x * vv0.x;
                acc[k].y += p.x * vv0.y;
                acc[k].z += p.x * vv0.z;
                acc[k].w += p.x * vv0.w;
                acc[k].x += p.y * vv1.x;
                acc[k].y += p.y * vv1.y;
                acc[k].z += p.y * vv1.z;
                acc[k].w += p.y * vv1.w;
                acc[k].x += p.z * vv2.x;
                acc[k].y += p.z * vv2.y;
                acc[k].z += p.z * vv2.z;
                acc[k].w += p.z * vv2.w;
                acc[k].x += p.w * vv3.x;
                acc[k].y += p.w * vv3.y;
                acc[k].z += p.w * vv3.z;
                acc[k].w += p.w * vv3.w;
            }
        }
        __syncthreads();   // all Ss (P) reads done before overwriting Ss with partials
#pragma unroll
        for (int k = 0; k < 5; k++) {
            int u = ublk * 5 + k;
            *(float4*)(Ss + (jh * NT + u) * 64 + (d4 << 2)) = acc[k];
        }
    }
    __syncthreads();

    // partial add + write (float4)
    {
        const float4* Ss4 = (const float4*)Ss;
        float4* po4 = (float4*)(g_po + (size_t)(bh * NSPLIT + split) * NT * DD);
        for (int i = t; i < NT * 16; i += 256) {
            float4 a = Ss4[i];
            float4 c = Ss4[NT * 16 + i];
            a.x += c.x; a.y += c.y; a.z += c.z; a.w += c.w;
            po4[i] = a;
        }
    }
}

// ---------------- combine v2 (proven, frozen) ----------------
__global__ void combine_kernel(float* __restrict__ out) {
    __shared__ float sw[5 * NSPLIT];
    __shared__ float sl[5];
    int bid = blockIdx.x;
    int bh = bid >> 3, uc = bid & 7;
    int b = bh >> 3, h = bh & 7;
    int t = threadIdx.x;

    if (t < 5) {
        int u = uc * 5 + t;
        float m = -3e38f;
#pragma unroll
        for (int s = 0; s < NSPLIT; s++)
            m = fmaxf(m, g_pm[(bh * NSPLIT + s) * NT + u]);
        float Ls = 0.f;
#pragma unroll
        for (int s = 0; s < NSPLIT; s++) {
            float w = __expf(g_pm[(bh * NSPLIT + s) * NT + u] - m);
            sw[t * NSPLIT + s] = w;
            Ls += g_pl[(bh * NSPLIT + s) * NT + u] * w;
        }
        sl[t] = Ls;
    }
    __syncthreads();
    for (int i = t; i < 5 * DD; i += 256) {
        int uu = i >> 6, d = i & 63;
        int u = uc * 5 + uu;
        float acc = 0.f;
#pragma unroll
        for (int s = 0; s < NSPLIT; s++)
            acc += sw[uu * NSPLIT + s] *
                   g_po[(size_t)(bh * NSPLIT + s) * NT * DD + u * DD + d];
        out[(((size_t)(b * NT + u) * HH + h) << 6) + d] = acc / sl[uu];
    }
}

// ---------------- launcher ----------------
extern "C" void kernel_launch(void* const* d_in, const int* in_sizes, int n_in,
                              void* d_out, int out_size) {
    const float* Q   = (const float*)d_in[0];
    const float* K   = (const float*)d_in[1];
    const float* V   = (const float*)d_in[2];
    const void*  idx = d_in[3];

    detect_idx_kernel<<<1, 32>>>((const long long*)idx);
    sample_m_kernel<<<(BHN * LL) / 8, 256>>>(Q, K, idx);
    topk_kernel<<<BHN, 32>>>();

    size_t smemD = (size_t)(NT * DD + 64 * KTPAD + NT * CHUNK) * sizeof(float); // 64512
    cudaFuncSetAttribute(attn_kernel, cudaFuncAttributeMaxDynamicSharedMemorySize, (int)smemD);
    attn_kernel<<<BHN * NSPLIT, 256, smemD>>>(Q, K, V);

    combine_kernel<<<BHN * 8, 256>>>((float*)d_out);
}

// round 11
// speedup vs baseline: 1.0531x; 1.0156x over previous
#include <cuda_runtime.h>
#include <cstddef>

#define BB 4
#define LL 2048
#define HH 8
#define DD 64
#define SK 40
#define NT 40
#define BHN 32
#define NSPLIT 16
#define CHUNK 128
#define KTPAD 132
#define SCALE 0.125f

// ---------------- scratch ----------------
__device__ float g_M[BHN * LL];
__device__ int   g_top[BHN * NT];
__device__ float g_pm[BHN * NSPLIT * NT];
__device__ float g_pl[BHN * NSPLIT * NT];
__device__ float g_po[BHN * NSPLIT * NT * DD];
__device__ int   g_cnt1[BHN];   // zero-init; self-resetting
__device__ int   g_cnt2[BHN];   // zero-init; self-resetting

// ================= kernel 1: sample_m + inline detect + fused topk =================
__global__ void sample_m_kernel(const float* __restrict__ Q,
                                const float* __restrict__ K,
                                const void*  __restrict__ idxbuf) {
    __shared__ float sM[LL];      // used only by the topk tail
    __shared__ int   s_last;

    int wid  = (blockIdx.x * blockDim.x + threadIdx.x) >> 5;
    int lane = threadIdx.x & 31;
    int l  = wid % LL;
    int bh = wid / LL;
    int b = bh >> 3, h = bh & 7;
    int g  = lane >> 3;
    int li = lane & 7;

    // ---- inline dtype detection: read only the first 32 int64 slots (safe) ----
    {
        long long v = ((const long long*)idxbuf)[lane];
        int ok = (v >= 0 && v < LL);
        unsigned m = __ballot_sync(0xffffffffu, ok);
        int is64 = (m == 0xffffffffu);

        int ia, ib = 0;
        if (is64) {
            const long long* p = (const long long*)idxbuf + (long long)l * SK;
            ia = (int)p[lane];
            if (lane < SK - 32) ib = (int)p[32 + lane];
        } else {
            const int* p = (const int*)idxbuf + l * SK;
            ia = p[lane];
            if (lane < SK - 32) ib = p[32 + lane];
        }

        const float* qbase = Q + (((size_t)(b * LL + l) * HH + h) << 6) + (li << 3);
        const float4 qa = ((const float4*)qbase)[0];
        const float4 qb = ((const float4*)qbase)[1];

        const size_t kstride_h = ((size_t)h << 6) + ((size_t)li << 3);
        const float* Kb = K + ((size_t)b * LL * HH << 6);

        float mx = -3e38f, sm = 0.0f;
#pragma unroll
        for (int r = 0; r < 10; r++) {
            int s = 4 * r + g;
            int j = (s < 32) ? __shfl_sync(0xffffffffu, ia, s)
                             : __shfl_sync(0xffffffffu, ib, s - 32);
            const float4* kp = (const float4*)(Kb + (((size_t)j * HH) << 6) + kstride_h);
            float4 k0 = kp[0];
            float4 k1 = kp[1];
            float p = qa.x * k0.x;
            p = fmaf(qa.y, k0.y, p);
            p = fmaf(qa.z, k0.z, p);
            p = fmaf(qa.w, k0.w, p);
            p = fmaf(qb.x, k1.x, p);
            p = fmaf(qb.y, k1.y, p);
            p = fmaf(qb.z, k1.z, p);
            p = fmaf(qb.w, k1.w, p);
            p += __shfl_xor_sync(0xffffffffu, p, 1);
            p += __shfl_xor_sync(0xffffffffu, p, 2);
            p += __shfl_xor_sync(0xffffffffu, p, 4);
            mx = fmaxf(mx, p);
            sm += p;
        }
        mx = fmaxf(mx, __shfl_xor_sync(0xffffffffu, mx, 8));
        mx = fmaxf(mx, __shfl_xor_sync(0xffffffffu, mx, 16));
        sm += __shfl_xor_sync(0xffffffffu, sm, 8);
        sm += __shfl_xor_sync(0xffffffffu, sm, 16);
        if (lane == 0) g_M[bh * LL + l] = mx - sm * (1.0f / (float)LL);
    }

    // ---- fused topk: last block of this bh (256 blocks per bh) runs topk ----
    __syncthreads();
    __threadfence();
    if (threadIdx.x == 0)
        s_last = (atomicAdd(&g_cnt1[bh], 1) == 255) ? 1 : 0;
    __syncthreads();
    if (!s_last) return;

    if (threadIdx.x < 32) {       // warp 0: proven topk-v3
        for (int i = lane; i < LL; i += 32) sM[i] = g_M[bh * LL + i];
        __syncwarp();

        int base = lane << 6;
        unsigned long long s0 = 0ull, s1 = 0ull, s2 = 0ull;
#pragma unroll 4
        for (int i = 0; i < 64; i++) {
            float x = sM[base + i];
            unsigned uv = __float_as_uint(x);
            uv ^= (uv >> 31) ? 0xffffffffu : 0x80000000u;
            unsigned long long k = ((unsigned long long)uv << 32)
                                 | (unsigned)(LL - 1 - (base + i));
            if (k > s0)      { s2 = s1; s1 = s0; s0 = k; }
            else if (k > s1) { s2 = s1; s1 = k; }
            else if (k > s2) { s2 = k; }
        }
        for (int it = 0; it < NT; it++) {
            unsigned ord0 = (unsigned)(s0 >> 32);
            unsigned m1 = __reduce_max_sync(0xffffffffu, ord0);
            unsigned lowp = (ord0 == m1) ? ((unsigned)s0 + 1u) : 0u;
            unsigned m2 = __reduce_max_sync(0xffffffffu, lowp);
            int wi = LL - (int)m2;
            if (lane == 0) g_top[bh * NT + it] = wi;
            if (lane == (wi >> 6)) {
                sM[wi] = -3e38f;
                s0 = s1; s1 = s2; s2 = 0ull;
                if (s0 == 0ull) {
                    for (int i = 0; i < 64; i++) {
                        float x = sM[base + i];
                        unsigned uv = __float_as_uint(x);
                        uv ^= (uv >> 31) ? 0xffffffffu : 0x80000000u;
                        unsigned long long k = ((unsigned long long)uv << 32)
                                             | (unsigned)(LL - 1 - (base + i));
                        if (k > s0)      { s2 = s1; s1 = s0; s0 = k; }
                        else if (k > s1) { s2 = s1; s1 = k; }
                        else if (k > s2) { s2 = k; }
                    }
                }
            }
            __syncwarp();
        }
        if (lane == 0) g_cnt1[bh] = 0;   // reset for next graph replay
    }
}

// ================= kernel 2: attn (R10-proven body) + fused combine =================
__global__ void __launch_bounds__(256, 3)
attn_kernel(const float* __restrict__ Q,
            const float* __restrict__ K,
            const float* __restrict__ V,
            float* __restrict__ out) {
    extern __shared__ float smem[];
    __shared__ int s_last;
    int bh = blockIdx.x / NSPLIT, split = blockIdx.x % NSPLIT;
    int b = bh >> 3, h = bh & 7;
    int t = threadIdx.x;

    float* Qs = smem;                  // 2560
    float* KV = Qs + NT * DD;          // 8448
    float* Ss = KV + 64 * KTPAD;       // 5120

    for (int i = t; i < NT * 16; i += 256) {
        int u = i >> 4, c = i & 15;
        int ql = g_top[bh * NT + u];
        ((float4*)Qs)[i] =
            ((const float4*)Q)[(((size_t)(b * LL + ql) * HH + h) << 4) + c];
    }
    int key0 = split * CHUNK;
    for (int i = t; i < CHUNK * DD; i += 256) {
        int j = i >> 6, d = i & 63;
        KV[d * KTPAD + j] = K[(((size_t)(b * LL + key0 + j) * HH + h) << 6) + d];
    }
    __syncthreads();

    // ---- phase 1: scores ----
    {
        int ublk = t >> 5;
        int jg   = t & 31;
        float4 acc[5];
#pragma unroll
        for (int k = 0; k < 5; k++) acc[k] = make_float4(0.f, 0.f, 0.f, 0.f);
        const float4* Kt4 = (const float4*)KV;
#pragma unroll 4
        for (int d = 0; d < 64; d += 4) {
            float4 kv0 = Kt4[(d + 0) * 33 + jg];
            float4 kv1 = Kt4[(d + 1) * 33 + jg];
            float4 kv2 = Kt4[(d + 2) * 33 + jg];
            float4 kv3 = Kt4[(d + 3) * 33 + jg];
#pragma unroll
            for (int k = 0; k < 5; k++) {
                float4 qv = *(const float4*)(Qs + (ublk * 5 + k) * 64 + d);
                acc[k].x += qv.x * kv0.x;
                acc[k].y += qv.x * kv0.y;
                acc[k].z += qv.x * kv0.z;
                acc[k].w += qv.x * kv0.w;
                acc[k].x += qv.y * kv1.x;
                acc[k].y += qv.y * kv1.y;
                acc[k].z += qv.y * kv1.z;
                acc[k].w += qv.y * kv1.w;
                acc[k].x += qv.z * kv2.x;
                acc[k].y += qv.z * kv2.y;
                acc[k].z += qv.z * kv2.z;
                acc[k].w += qv.z * kv2.w;
                acc[k].x += qv.w * kv3.x;
                acc[k].y += qv.w * kv3.y;
                acc[k].z += qv.w * kv3.z;
                acc[k].w += qv.w * kv3.w;
            }
        }
#pragma unroll
        for (int k = 0; k < 5; k++) {
            int u = ublk * 5 + k;
            float4 sv = make_float4(acc[k].x * SCALE, acc[k].y * SCALE,
                                    acc[k].z * SCALE, acc[k].w * SCALE);
            *(float4*)(Ss + u * CHUNK + (jg << 2)) = sv;
        }
    }
    __syncwarp();

    // ---- phase 1.5: partial softmax ----
    {
        int w = t >> 5, lane = t & 31;
        for (int r = w * 5; r < w * 5 + 5; r++) {
            float v0 = Ss[r * CHUNK + lane];
            float v1 = Ss[r * CHUNK + lane + 32];
            float v2 = Ss[r * CHUNK + lane + 64];
            float v3 = Ss[r * CHUNK + lane + 96];
            float m = fmaxf(fmaxf(v0, v1), fmaxf(v2, v3));
#pragma unroll
            for (int o = 16; o; o >>= 1) m = fmaxf(m, __shfl_xor_sync(0xffffffffu, m, o));
            float e0 = __expf(v0 - m), e1 = __expf(v1 - m);
            float e2 = __expf(v2 - m), e3 = __expf(v3 - m);
            Ss[r * CHUNK + lane]      = e0;
            Ss[r * CHUNK + lane + 32] = e1;
            Ss[r * CHUNK + lane + 64] = e2;
            Ss[r * CHUNK + lane + 96] = e3;
            float s = e0 + e1 + e2 + e3;
#pragma unroll
            for (int o = 16; o; o >>= 1) s += __shfl_xor_sync(0xffffffffu, s, o);
            if (lane == 0) {
                g_pm[(bh * NSPLIT + split) * NT + r] = m;
                g_pl[(bh * NSPLIT + split) * NT + r] = s;
            }
        }
    }
    __syncthreads();

    // ---- deferred V staging ----
    for (int i = t; i < CHUNK * 16; i += 256) {
        int j = i >> 4, c = i & 15;
        ((float4*)KV)[i] =
            ((const float4*)V)[(((size_t)(b * LL + key0 + j) * HH + h) << 4) + c];
    }
    __syncthreads();

    // ---- phase 2: O_partial = P @ V ----
    {
        int ublk = t >> 5;
        int d4   = t & 15;
        int jh   = (t >> 4) & 1;
        float4 acc[5];
#pragma unroll
        for (int k = 0; k < 5; k++) acc[k] = make_float4(0.f, 0.f, 0.f, 0.f);
        const float4* Vs4 = (const float4*)KV;
        int j0 = jh * 64;
#pragma unroll 4
        for (int jj = 0; jj < 64; jj += 4) {
            int j = j0 + jj;
            float4 vv0 = Vs4[(j + 0) * 16 + d4];
            float4 vv1 = Vs4[(j + 1) * 16 + d4];
            float4 vv2 = Vs4[(j + 2) * 16 + d4];
            float4 vv3 = Vs4[(j + 3) * 16 + d4];
#pragma unroll
            for (int k = 0; k < 5; k++) {
                float4 p = *(const float4*)(Ss + (ublk * 5 + k) * CHUNK + j);
                acc[k].x += p.x * vv0.x;
                acc[k].y += p.x * vv0.y;
                acc[k].z += p.x * vv0.z;
                acc[k].w += p.x * vv0.w;
                acc[k].x += p.y * vv1.x;
                acc[k].y += p.y * vv1.y;
                acc[k].z += p.y * vv1.z;
                acc[k].w += p.y * vv1.w;
                acc[k].x += p.z * vv2.x;
                acc[k].y += p.z * vv2.y;
                acc[k].z += p.z * vv2.z;
                acc[k].w += p.z * vv2.w;
                acc[k].x += p.w * vv3.x;
                acc[k].y += p.w * vv3.y;
                acc[k].z += p.w * vv3.z;
                acc[k].w += p.w * vv3.w;
            }
        }
        __syncthreads();
#pragma unroll
        for (int k = 0; k < 5; k++) {
            int u = ublk * 5 + k;
            *(float4*)(Ss + (jh * NT + u) * 64 + (d4 << 2)) = acc[k];
        }
    }
    __syncthreads();

    {
        const float4* Ss4 = (const float4*)Ss;
        float4* po4 = (float4*)(g_po + (size_t)(bh * NSPLIT + split) * NT * DD);
        for (int i = t; i < NT * 16; i += 256) {
            float4 a = Ss4[i];
            float4 c = Ss4[NT * 16 + i];
            a.x += c.x; a.y += c.y; a.z += c.z; a.w += c.w;
            po4[i] = a;
        }
    }

    // ---- fused combine: last split-block of this bh ----
    __syncthreads();
    __threadfence();
    if (t == 0)
        s_last = (atomicAdd(&g_cnt2[bh], 1) == NSPLIT - 1) ? 1 : 0;
    __syncthreads();
    if (!s_last) return;

    float* sw = smem;            // 40*16 = 640 floats (Qs region, dead)
    float* sl = smem + 640;      // 40
    if (t < NT) {
        float m = -3e38f;
#pragma unroll
        for (int s = 0; s < NSPLIT; s++)
            m = fmaxf(m, g_pm[(bh * NSPLIT + s) * NT + t]);
        float Ls = 0.f;
#pragma unroll
        for (int s = 0; s < NSPLIT; s++) {
            float w = __expf(g_pm[(bh * NSPLIT + s) * NT + t] - m);
            sw[t * NSPLIT + s] = w;
            Ls += g_pl[(bh * NSPLIT + s) * NT + t] * w;
        }
        sl[t] = Ls;
    }
    __syncthreads();
    for (int i = t; i < NT * DD; i += 256) {
        int u = i >> 6, d = i & 63;
        float acc = 0.f;
#pragma unroll
        for (int s = 0; s < NSPLIT; s++)
            acc += sw[u * NSPLIT + s] *
                   g_po[(size_t)(bh * NSPLIT + s) * NT * DD + i];
        out[(((size_t)(b * NT + u) * HH + h) << 6) + d] = acc / sl[u];
    }
    __syncthreads();
    if (t == 0) g_cnt2[bh] = 0;   // reset for next graph replay
}

// ---------------- launcher: 2 kernels ----------------
extern "C" void kernel_launch(void* const* d_in, const int* in_sizes, int n_in,
                              void* d_out, int out_size) {
    const float* Q   = (const float*)d_in[0];
    const float* K   = (const float*)d_in[1];
    const float* V   = (const float*)d_in[2];
    const void*  idx = d_in[3];

    sample_m_kernel<<<(BHN * LL) / 8, 256>>>(Q, K, idx);

    size_t smemD = (size_t)(NT * DD + 64 * KTPAD + NT * CHUNK) * sizeof(float); // 64512
    cudaFuncSetAttribute(attn_kernel, cudaFuncAttributeMaxDynamicSharedMemorySize, (int)smemD);
    attn_kernel<<<BHN * NSPLIT, 256, smemD>>>(Q, K, V, (float*)d_out);
}